// round 12
// baseline (speedup 1.0000x reference)
#include <cuda_runtime.h>

#define BATCH  8
#define SEQ    512
#define NHEAD  8
#define HDIM   64
#define DMODEL 512
#define NREL   1023
#define ZOFF   511

typedef unsigned long long ull;

// Scratch (allocation-free rule: __device__ globals)
__device__ float g_Q[BATCH*NHEAD*SEQ*HDIM];
__device__ float g_K[BATCH*NHEAD*SEQ*HDIM];
__device__ float g_V[BATCH*NHEAD*SEQ*HDIM];
__device__ float g_ctx[BATCH*SEQ*DMODEL];

// ---- tf32 helpers -----------------------------------------------------------
__device__ __forceinline__ float f2tf(float f) {
    unsigned u;
    asm("cvt.rna.tf32.f32 %0, %1;" : "=r"(u) : "f"(f));
    return __uint_as_float(u);
}

__device__ __forceinline__ void mma_tf32(float* c, const unsigned* a, const unsigned* b) {
    asm("mma.sync.aligned.m16n8k8.row.col.f32.tf32.tf32.f32 "
        "{%0,%1,%2,%3}, {%4,%5,%6,%7}, {%8,%9}, {%0,%1,%2,%3};"
        : "+f"(c[0]), "+f"(c[1]), "+f"(c[2]), "+f"(c[3])
        : "r"(a[0]), "r"(a[1]), "r"(a[2]), "r"(a[3]), "r"(b[0]), "r"(b[1]));
}

// Paired-k helpers: smem stores {x[k], x[k+4]} adjacently -> LDS.64 loads.
// row index for element k: (k>>3)*4 + (k&3); half: (k>>2)&1.

// ---------------------------------------------------------------------------
// 128x64x(BK=16) tf32 GEMM, paired-k smem layout (LDS.64 fragment loads).
// ---------------------------------------------------------------------------
__global__ void __launch_bounds__(256) qkv_gemm_kernel(
    const float* __restrict__ X,
    const float* __restrict__ Wq, const float* __restrict__ bq,
    const float* __restrict__ Wk, const float* __restrict__ bk,
    const float* __restrict__ Wv, const float* __restrict__ bv)
{
    const int z = blockIdx.z;
    const float* __restrict__ W    = (z==0) ? Wq : (z==1) ? Wk : Wv;
    const float* __restrict__ bias = (z==0) ? bq : (z==1) ? bk : bv;
    float* out = (z==0) ? g_Q : (z==1) ? g_K : g_V;

    // paired-k: [kgroup*4 + t][m*2 + half]; row strides 264/136 (≡8 mod 32 banks)
    __shared__ float As2[2][8][264];
    __shared__ float Bs2[2][8][136];

    const int m0 = blockIdx.y * 128;
    const int n0 = blockIdx.x * 64;
    const int tid = threadIdx.x;
    const int wid = tid >> 5;
    const int lane = tid & 31;
    const int g   = lane >> 2;
    const int tig = lane & 3;
    const int wm = (wid >> 1) * 32;
    const int wn = (wid & 1) * 32;

    const int am = tid >> 2;          // 0..63 (and +64)
    const int ak = (tid & 3) * 4;     // 0,4,8,12
    const int bkr = tid >> 4;         // 0..15
    const int bn = (tid & 15) * 4;

    // staging decomposition for A: k = ak + c
    const int a_kg   = ak >> 3;          // 0 or 1
    const int a_half = (ak >> 2) & 1;    // 0 or 1
    // B: k = bkr
    const int b_row  = (bkr >> 3)*4 + (bkr & 3);
    const int b_half = (bkr >> 2) & 1;

    float4 xa0, xa1, wb0;
    float acc[2][4][4];
    #pragma unroll
    for (int mt = 0; mt < 2; mt++)
        #pragma unroll
        for (int nt = 0; nt < 4; nt++)
            #pragma unroll
            for (int c = 0; c < 4; c++) acc[mt][nt][c] = 0.f;

    {
        const float* Xp = X + (size_t)m0 * DMODEL;
        xa0 = *(const float4*)&Xp[(size_t)am * DMODEL + ak];
        xa1 = *(const float4*)&Xp[(size_t)(am + 64) * DMODEL + ak];
        wb0 = *(const float4*)&W[(size_t)bkr * DMODEL + n0 + bn];
        As2[0][a_kg*4+0][am*2 + a_half] = f2tf(xa0.x);
        As2[0][a_kg*4+1][am*2 + a_half] = f2tf(xa0.y);
        As2[0][a_kg*4+2][am*2 + a_half] = f2tf(xa0.z);
        As2[0][a_kg*4+3][am*2 + a_half] = f2tf(xa0.w);
        As2[0][a_kg*4+0][(am+64)*2 + a_half] = f2tf(xa1.x);
        As2[0][a_kg*4+1][(am+64)*2 + a_half] = f2tf(xa1.y);
        As2[0][a_kg*4+2][(am+64)*2 + a_half] = f2tf(xa1.z);
        As2[0][a_kg*4+3][(am+64)*2 + a_half] = f2tf(xa1.w);
        Bs2[0][b_row][(bn+0)*2 + b_half] = f2tf(wb0.x);
        Bs2[0][b_row][(bn+1)*2 + b_half] = f2tf(wb0.y);
        Bs2[0][b_row][(bn+2)*2 + b_half] = f2tf(wb0.z);
        Bs2[0][b_row][(bn+3)*2 + b_half] = f2tf(wb0.w);
    }
    __syncthreads();

    int buf = 0;
    for (int kt = 0; kt < 32; kt++) {
        if (kt < 31) {
            const float* Xp = X + (size_t)m0 * DMODEL + (kt+1)*16;
            xa0 = *(const float4*)&Xp[(size_t)am * DMODEL + ak];
            xa1 = *(const float4*)&Xp[(size_t)(am + 64) * DMODEL + ak];
            wb0 = *(const float4*)&W[((size_t)(kt+1)*16 + bkr) * DMODEL + n0 + bn];
        }
        #pragma unroll
        for (int kg = 0; kg < 2; kg++) {
            unsigned afr[2][4], bfr[4][2];
            #pragma unroll
            for (int mt = 0; mt < 2; mt++) {
                float2 aLo = *(const float2*)&As2[buf][kg*4+tig][(wm+mt*16+g)*2];
                float2 aHi = *(const float2*)&As2[buf][kg*4+tig][(wm+mt*16+g+8)*2];
                afr[mt][0] = __float_as_uint(aLo.x);
                afr[mt][1] = __float_as_uint(aHi.x);
                afr[mt][2] = __float_as_uint(aLo.y);
                afr[mt][3] = __float_as_uint(aHi.y);
            }
            #pragma unroll
            for (int nt = 0; nt < 4; nt++) {
                float2 bb = *(const float2*)&Bs2[buf][kg*4+tig][(wn+nt*8+g)*2];
                bfr[nt][0] = __float_as_uint(bb.x);
                bfr[nt][1] = __float_as_uint(bb.y);
            }
            #pragma unroll
            for (int mt = 0; mt < 2; mt++)
                #pragma unroll
                for (int nt = 0; nt < 4; nt++)
                    mma_tf32(acc[mt][nt], afr[mt], bfr[nt]);
        }
        if (kt < 31) {
            int nb = buf ^ 1;
            As2[nb][a_kg*4+0][am*2 + a_half] = f2tf(xa0.x);
            As2[nb][a_kg*4+1][am*2 + a_half] = f2tf(xa0.y);
            As2[nb][a_kg*4+2][am*2 + a_half] = f2tf(xa0.z);
            As2[nb][a_kg*4+3][am*2 + a_half] = f2tf(xa0.w);
            As2[nb][a_kg*4+0][(am+64)*2 + a_half] = f2tf(xa1.x);
            As2[nb][a_kg*4+1][(am+64)*2 + a_half] = f2tf(xa1.y);
            As2[nb][a_kg*4+2][(am+64)*2 + a_half] = f2tf(xa1.z);
            As2[nb][a_kg*4+3][(am+64)*2 + a_half] = f2tf(xa1.w);
            Bs2[nb][b_row][(bn+0)*2 + b_half] = f2tf(wb0.x);
            Bs2[nb][b_row][(bn+1)*2 + b_half] = f2tf(wb0.y);
            Bs2[nb][b_row][(bn+2)*2 + b_half] = f2tf(wb0.z);
            Bs2[nb][b_row][(bn+3)*2 + b_half] = f2tf(wb0.w);
        }
        __syncthreads();
        buf ^= 1;
    }

    const int hh = n0 >> 6;
    #pragma unroll
    for (int mt = 0; mt < 2; mt++) {
        int r0 = m0 + wm + mt*16 + g;
        int r1 = r0 + 8;
        int bb0 = r0 >> 9, ii0 = r0 & 511;
        int bb1 = r1 >> 9, ii1 = r1 & 511;
        float* op0 = &out[(((size_t)(bb0*NHEAD + hh)*SEQ) + ii0)*HDIM];
        float* op1 = &out[(((size_t)(bb1*NHEAD + hh)*SEQ) + ii1)*HDIM];
        #pragma unroll
        for (int nt = 0; nt < 4; nt++) {
            int dd = wn + nt*8 + tig*2;
            int n  = n0 + dd;
            float2 o0 = make_float2(acc[mt][nt][0] + bias[n], acc[mt][nt][1] + bias[n+1]);
            float2 o1 = make_float2(acc[mt][nt][2] + bias[n], acc[mt][nt][3] + bias[n+1]);
            *(float2*)&op0[dd] = o0;
            *(float2*)&op1[dd] = o1;
        }
    }
}

// ---------------------------------------------------------------------------
// Output projection — same paired-k structure.
// ---------------------------------------------------------------------------
__global__ void __launch_bounds__(256) out_gemm_kernel(
    const float* __restrict__ Wo, const float* __restrict__ bo,
    float* __restrict__ out)
{
    __shared__ float As2[2][8][264];
    __shared__ float Bs2[2][8][136];

    const int m0 = blockIdx.y * 128;
    const int n0 = blockIdx.x * 64;
    const int tid = threadIdx.x;
    const int wid = tid >> 5;
    const int lane = tid & 31;
    const int g   = lane >> 2;
    const int tig = lane & 3;
    const int wm = (wid >> 1) * 32;
    const int wn = (wid & 1) * 32;

    const int am = tid >> 2;
    const int ak = (tid & 3) * 4;
    const int bkr = tid >> 4;
    const int bn = (tid & 15) * 4;

    const int a_kg   = ak >> 3;
    const int a_half = (ak >> 2) & 1;
    const int b_row  = (bkr >> 3)*4 + (bkr & 3);
    const int b_half = (bkr >> 2) & 1;

    float4 xa0, xa1, wb0;
    float acc[2][4][4];
    #pragma unroll
    for (int mt = 0; mt < 2; mt++)
        #pragma unroll
        for (int nt = 0; nt < 4; nt++)
            #pragma unroll
            for (int c = 0; c < 4; c++) acc[mt][nt][c] = 0.f;

    {
        const float* Xp = g_ctx + (size_t)m0 * DMODEL;
        xa0 = *(const float4*)&Xp[(size_t)am * DMODEL + ak];
        xa1 = *(const float4*)&Xp[(size_t)(am + 64) * DMODEL + ak];
        wb0 = *(const float4*)&Wo[(size_t)bkr * DMODEL + n0 + bn];
        As2[0][a_kg*4+0][am*2 + a_half] = f2tf(xa0.x);
        As2[0][a_kg*4+1][am*2 + a_half] = f2tf(xa0.y);
        As2[0][a_kg*4+2][am*2 + a_half] = f2tf(xa0.z);
        As2[0][a_kg*4+3][am*2 + a_half] = f2tf(xa0.w);
        As2[0][a_kg*4+0][(am+64)*2 + a_half] = f2tf(xa1.x);
        As2[0][a_kg*4+1][(am+64)*2 + a_half] = f2tf(xa1.y);
        As2[0][a_kg*4+2][(am+64)*2 + a_half] = f2tf(xa1.z);
        As2[0][a_kg*4+3][(am+64)*2 + a_half] = f2tf(xa1.w);
        Bs2[0][b_row][(bn+0)*2 + b_half] = f2tf(wb0.x);
        Bs2[0][b_row][(bn+1)*2 + b_half] = f2tf(wb0.y);
        Bs2[0][b_row][(bn+2)*2 + b_half] = f2tf(wb0.z);
        Bs2[0][b_row][(bn+3)*2 + b_half] = f2tf(wb0.w);
    }
    __syncthreads();

    int buf = 0;
    for (int kt = 0; kt < 32; kt++) {
        if (kt < 31) {
            const float* Xp = g_ctx + (size_t)m0 * DMODEL + (kt+1)*16;
            xa0 = *(const float4*)&Xp[(size_t)am * DMODEL + ak];
            xa1 = *(const float4*)&Xp[(size_t)(am + 64) * DMODEL + ak];
            wb0 = *(const float4*)&Wo[((size_t)(kt+1)*16 + bkr) * DMODEL + n0 + bn];
        }
        #pragma unroll
        for (int kg = 0; kg < 2; kg++) {
            unsigned afr[2][4], bfr[4][2];
            #pragma unroll
            for (int mt = 0; mt < 2; mt++) {
                float2 aLo = *(const float2*)&As2[buf][kg*4+tig][(wm+mt*16+g)*2];
                float2 aHi = *(const float2*)&As2[buf][kg*4+tig][(wm+mt*16+g+8)*2];
                afr[mt][0] = __float_as_uint(aLo.x);
                afr[mt][1] = __float_as_uint(aHi.x);
                afr[mt][2] = __float_as_uint(aLo.y);
                afr[mt][3] = __float_as_uint(aHi.y);
            }
            #pragma unroll
            for (int nt = 0; nt < 4; nt++) {
                float2 bb = *(const float2*)&Bs2[buf][kg*4+tig][(wn+nt*8+g)*2];
                bfr[nt][0] = __float_as_uint(bb.x);
                bfr[nt][1] = __float_as_uint(bb.y);
            }
            #pragma unroll
            for (int mt = 0; mt < 2; mt++)
                #pragma unroll
                for (int nt = 0; nt < 4; nt++)
                    mma_tf32(acc[mt][nt], afr[mt], bfr[nt]);
        }
        if (kt < 31) {
            int nb = buf ^ 1;
            As2[nb][a_kg*4+0][am*2 + a_half] = f2tf(xa0.x);
            As2[nb][a_kg*4+1][am*2 + a_half] = f2tf(xa0.y);
            As2[nb][a_kg*4+2][am*2 + a_half] = f2tf(xa0.z);
            As2[nb][a_kg*4+3][am*2 + a_half] = f2tf(xa0.w);
            As2[nb][a_kg*4+0][(am+64)*2 + a_half] = f2tf(xa1.x);
            As2[nb][a_kg*4+1][(am+64)*2 + a_half] = f2tf(xa1.y);
            As2[nb][a_kg*4+2][(am+64)*2 + a_half] = f2tf(xa1.z);
            As2[nb][a_kg*4+3][(am+64)*2 + a_half] = f2tf(xa1.w);
            Bs2[nb][b_row][(bn+0)*2 + b_half] = f2tf(wb0.x);
            Bs2[nb][b_row][(bn+1)*2 + b_half] = f2tf(wb0.y);
            Bs2[nb][b_row][(bn+2)*2 + b_half] = f2tf(wb0.z);
            Bs2[nb][b_row][(bn+3)*2 + b_half] = f2tf(wb0.w);
        }
        __syncthreads();
        buf ^= 1;
    }

    #pragma unroll
    for (int mt = 0; mt < 2; mt++) {
        int r0 = m0 + wm + mt*16 + g;
        int r1 = r0 + 8;
        #pragma unroll
        for (int nt = 0; nt < 4; nt++) {
            int n = n0 + wn + nt*8 + tig*2;
            float2 o0 = make_float2(acc[mt][nt][0] + bo[n], acc[mt][nt][1] + bo[n+1]);
            float2 o1 = make_float2(acc[mt][nt][2] + bo[n], acc[mt][nt][3] + bo[n+1]);
            *(float2*)&out[(size_t)r0*DMODEL + n] = o0;
            *(float2*)&out[(size_t)r1*DMODEL + n] = o1;
        }
    }
}

// ---------------------------------------------------------------------------
// Fused attention: tensor-core phases with paired-k operand layout and split
// dependency chains (score by k-half; output mix vs band accumulators).
// ---------------------------------------------------------------------------
#define AOFF_QS   0                      // Qs2[32][72]               2304
#define AOFF_KS   2304                   // Ks2[32][136]              4352
#define AOFF_VS   6656                   // Vs2[32][136]              4352
#define AOFF_PVS  11008                  // Pvs2[48][136]             6528
#define AOFF_SC   17536                  // Sc[32][132] probs (cols 32..95), pads zero
#define AOFF_PK   21760                  // Pks[544]
#define AOFF_S    22304                  // srow[32]
#define ASM_TOT   22336
#define ATTN_SMEM_BYTES (ASM_TOT * 4)    // 89344 B -> 2 CTAs/SM

__global__ void __launch_bounds__(256, 2) attn_kernel(
    const float* __restrict__ Pk, const float* __restrict__ Pv)
{
    extern __shared__ float sm[];
    float* Qs2  = sm + AOFF_QS;    // [ (d>>3)*4 + (d&3) ][ il*2 + ((d>>2)&1) ], stride 72
    float* Ks2  = sm + AOFF_KS;    // [ k-row ][ j*2 + half ], stride 136
    float* Vs2  = sm + AOFF_VS;    // [ j-row ][ d*2 + half ], stride 136
    float* Pvs2 = sm + AOFF_PVS;   // [ r-row ][ d*2 + half ], stride 136
    float* Sc   = sm + AOFF_SC;
    float* Pks  = sm + AOFF_PK;
    float* srow = sm + AOFF_S;

    const int i0  = blockIdx.x * 32;
    const int h   = blockIdx.y;
    const int b   = blockIdx.z;
    const int tid = threadIdx.x;
    const int w   = tid >> 5;
    const int lane = tid & 31;
    const int g   = lane >> 2;
    const int tig = lane & 3;
    const int wm  = (w & 1) * 16;
    const int wn  = (w >> 1) * 16;

    const float* Qg = g_Q + (size_t)((b*NHEAD + h)*SEQ) * HDIM;
    const float* Kg = g_K + (size_t)((b*NHEAD + h)*SEQ) * HDIM;
    const float* Vg = g_V + (size_t)((b*NHEAD + h)*SEQ) * HDIM;

    // register prefetch (chunk 0)
    float  kp[16];
    float4 vp[4];
    #pragma unroll
    for (int it = 0; it < 16; it++) {
        int idx = tid + 256*it;
        kp[it] = Kg[(idx >> 6)*HDIM + (idx & 63)];
    }
    #pragma unroll
    for (int it = 0; it < 4; it++) {
        int f4 = tid + 256*it;
        vp[it] = *(const float4*)&Vg[(f4 >> 4)*HDIM + (f4 & 15)*4];
    }

    // Stage Q (paired-k), Pk slice, zero prob tile + srow
    #pragma unroll
    for (int idx = tid; idx < 32*64; idx += 256) {
        int dd = idx & 63, il = idx >> 6;
        Qs2[((dd>>3)*4 + (dd&3))*72 + il*2 + ((dd>>2)&1)] = f2tf(Qg[(i0+il)*HDIM + dd]);
    }
    const int rbase_k = ZOFF - i0 - 31;   // >= 0
    for (int r = tid; r < 543; r += 256)
        Pks[r] = Pk[(rbase_k + r)*NHEAD + h];
    for (int idx = tid; idx < 32*132; idx += 256)
        Sc[idx] = 0.f;
    if (tid < 32) srow[tid] = 0.f;

    // output accumulators: separate mix / band chains
    float accOm[2][4], accOb[2][4];
    #pragma unroll
    for (int nt = 0; nt < 2; nt++)
        #pragma unroll
        for (int c = 0; c < 4; c++) { accOm[nt][c] = 0.f; accOb[nt][c] = 0.f; }

    __syncthreads();

    for (int jc = 0; jc < 8; jc++) {
        const int j0 = jc * 64;

        // ---- STAGE: Pv LDG first, then STS (tf32, paired-k) ----
        const int rbase = ZOFF + j0 - i0 - 31;
        float4 pvl[6];
        #pragma unroll
        for (int it = 0; it < 6; it++) {
            int f4 = tid + 256*it;
            int r = f4 >> 4, dq = f4 & 15;
            int rr = rbase + r;
            rr = (rr < 0) ? 0 : (rr > NREL-1) ? NREL-1 : rr;
            pvl[it] = *(const float4*)&Pv[((size_t)rr*NHEAD + h)*HDIM + dq*4];
        }
        #pragma unroll
        for (int it = 0; it < 16; it++) {
            int idx = tid + 256*it;
            int dd = idx & 63, j = idx >> 6;
            Ks2[((dd>>3)*4 + (dd&3))*136 + j*2 + ((dd>>2)&1)] = f2tf(kp[it]);
        }
        #pragma unroll
        for (int it = 0; it < 4; it++) {
            int f4 = tid + 256*it;
            int j = f4 >> 4, dq = f4 & 15;
            float* vd = &Vs2[((j>>3)*4 + (j&3))*136 + ((j>>2)&1)];
            vd[(dq*4+0)*2] = f2tf(vp[it].x);
            vd[(dq*4+1)*2] = f2tf(vp[it].y);
            vd[(dq*4+2)*2] = f2tf(vp[it].z);
            vd[(dq*4+3)*2] = f2tf(vp[it].w);
        }
        #pragma unroll
        for (int it = 0; it < 6; it++) {
            int f4 = tid + 256*it;
            int r = f4 >> 4, dq = f4 & 15;
            float* pd = &Pvs2[((r>>3)*4 + (r&3))*136 + ((r>>2)&1)];
            pd[(dq*4+0)*2] = f2tf(pvl[it].x);
            pd[(dq*4+1)*2] = f2tf(pvl[it].y);
            pd[(dq*4+2)*2] = f2tf(pvl[it].z);
            pd[(dq*4+3)*2] = f2tf(pvl[it].w);
        }
        __syncthreads();

        // ---- prefetch next chunk's K/V ----
        if (jc < 7) {
            const int jn = j0 + 64;
            #pragma unroll
            for (int it = 0; it < 16; it++) {
                int idx = tid + 256*it;
                kp[it] = Kg[(jn + (idx >> 6))*HDIM + (idx & 63)];
            }
            #pragma unroll
            for (int it = 0; it < 4; it++) {
                int f4 = tid + 256*it;
                vp[it] = *(const float4*)&Vg[(jn + (f4 >> 4))*HDIM + (f4 & 15)*4];
            }
        }

        // ---- SCORE mma (split chains: k8 0..3 and 4..7) ----
        {
            float scA[2][4], scB[2][4];
            #pragma unroll
            for (int nt = 0; nt < 2; nt++)
                #pragma unroll
                for (int c = 0; c < 4; c++) { scA[nt][c] = 0.f; scB[nt][c] = 0.f; }

            #pragma unroll
            for (int k8 = 0; k8 < 8; k8++) {
                unsigned qa[4], kb[2][2];
                float2 qLo = *(const float2*)&Qs2[(k8*4+tig)*72 + (wm+g)*2];
                float2 qHi = *(const float2*)&Qs2[(k8*4+tig)*72 + (wm+g+8)*2];
                qa[0] = __float_as_uint(qLo.x); qa[1] = __float_as_uint(qHi.x);
                qa[2] = __float_as_uint(qLo.y); qa[3] = __float_as_uint(qHi.y);
                #pragma unroll
                for (int nt = 0; nt < 2; nt++) {
                    float2 bb = *(const float2*)&Ks2[(k8*4+tig)*136 + (wn+nt*8+g)*2];
                    kb[nt][0] = __float_as_uint(bb.x);
                    kb[nt][1] = __float_as_uint(bb.y);
                }
                if (k8 < 4) { mma_tf32(scA[0], qa, kb[0]); mma_tf32(scA[1], qa, kb[1]); }
                else        { mma_tf32(scB[0], qa, kb[0]); mma_tf32(scB[1], qa, kb[1]); }
            }

            // exp + store probs (tf32) + row sums
            const int il_lo = wm + g;
            const int il_hi = il_lo + 8;
            float rs_lo = 0.f, rs_hi = 0.f;
            #pragma unroll
            for (int nt = 0; nt < 2; nt++) {
                int jj0 = wn + nt*8 + tig*2;
                float s0 = scA[nt][0] + scB[nt][0];
                float s1 = scA[nt][1] + scB[nt][1];
                float s2 = scA[nt][2] + scB[nt][2];
                float s3 = scA[nt][3] + scB[nt][3];
                float p0 = __expf((s0 + Pks[j0 + jj0     + 31 - il_lo]) * 0.125f);
                float p1 = __expf((s1 + Pks[j0 + jj0 + 1 + 31 - il_lo]) * 0.125f);
                float p2 = __expf((s2 + Pks[j0 + jj0     + 31 - il_hi]) * 0.125f);
                float p3 = __expf((s3 + Pks[j0 + jj0 + 1 + 31 - il_hi]) * 0.125f);
                p0 = f2tf(p0); p1 = f2tf(p1); p2 = f2tf(p2); p3 = f2tf(p3);
                Sc[il_lo*132 + 32 + jj0    ] = p0;
                Sc[il_lo*132 + 32 + jj0 + 1] = p1;
                Sc[il_hi*132 + 32 + jj0    ] = p2;
                Sc[il_hi*132 + 32 + jj0 + 1] = p3;
                rs_lo += p0 + p1;
                rs_hi += p2 + p3;
            }
            rs_lo += __shfl_xor_sync(0xffffffffu, rs_lo, 1);
            rs_lo += __shfl_xor_sync(0xffffffffu, rs_lo, 2);
            rs_hi += __shfl_xor_sync(0xffffffffu, rs_hi, 1);
            rs_hi += __shfl_xor_sync(0xffffffffu, rs_hi, 2);
            if (tig == 0) {
                atomicAdd(&srow[il_lo], rs_lo);
                atomicAdd(&srow[il_hi], rs_hi);
            }
        }
        __syncthreads();

        // ---- MIX mma: accOm += P V ----
        #pragma unroll
        for (int k8 = 0; k8 < 8; k8++) {
            unsigned pa[4], vb[2][2];
            pa[0] = __float_as_uint(Sc[(wm+g  )*132 + 32 + k8*8 + tig]);
            pa[1] = __float_as_uint(Sc[(wm+g+8)*132 + 32 + k8*8 + tig]);
            pa[2] = __float_as_uint(Sc[(wm+g  )*132 + 32 + k8*8 + tig + 4]);
            pa[3] = __float_as_uint(Sc[(wm+g+8)*132 + 32 + k8*8 + tig + 4]);
            #pragma unroll
            for (int nt = 0; nt < 2; nt++) {
                float2 bb = *(const float2*)&Vs2[(k8*4+tig)*136 + (wn+nt*8+g)*2];
                vb[nt][0] = __float_as_uint(bb.x);
                vb[nt][1] = __float_as_uint(bb.y);
            }
            mma_tf32(accOm[0], pa, vb[0]);
            mma_tf32(accOm[1], pa, vb[1]);
        }
        // ---- BAND mma: accOb += Pshift Pvs  (A[il][r] = Sc[il][il+r+1]) ----
        #pragma unroll
        for (int k12 = 0; k12 < 12; k12++) {
            unsigned pa[4], vb[2][2];
            const int r0 = k12*8 + tig;
            pa[0] = __float_as_uint(Sc[(wm+g  )*132 + (wm+g  ) + r0 + 1]);
            pa[1] = __float_as_uint(Sc[(wm+g+8)*132 + (wm+g+8) + r0 + 1]);
            pa[2] = __float_as_uint(Sc[(wm+g  )*132 + (wm+g  ) + r0 + 5]);
            pa[3] = __float_as_uint(Sc[(wm+g+8)*132 + (wm+g+8) + r0 + 5]);
            #pragma unroll
            for (int nt = 0; nt < 2; nt++) {
                float2 bb = *(const float2*)&Pvs2[(k12*4+tig)*136 + (wn+nt*8+g)*2];
                vb[nt][0] = __float_as_uint(bb.x);
                vb[nt][1] = __float_as_uint(bb.y);
            }
            mma_tf32(accOb[0], pa, vb[0]);
            mma_tf32(accOb[1], pa, vb[1]);
        }
        __syncthreads();
    }

    // ---- normalize + write context ----
    {
        const int il_lo = wm + g;
        const int il_hi = il_lo + 8;
        float inv_lo = 1.0f / srow[il_lo];
        float inv_hi = 1.0f / srow[il_hi];
        float* o_lo = &g_ctx[((size_t)(b*SEQ + i0 + il_lo))*DMODEL + h*HDIM];
        float* o_hi = &g_ctx[((size_t)(b*SEQ + i0 + il_hi))*DMODEL + h*HDIM];
        #pragma unroll
        for (int nt = 0; nt < 2; nt++) {
            int dd = wn + nt*8 + tig*2;
            float a0 = accOm[nt][0] + accOb[nt][0];
            float a1 = accOm[nt][1] + accOb[nt][1];
            float a2 = accOm[nt][2] + accOb[nt][2];
            float a3 = accOm[nt][3] + accOb[nt][3];
            *(float2*)&o_lo[dd] = make_float2(a0*inv_lo, a1*inv_lo);
            *(float2*)&o_hi[dd] = make_float2(a2*inv_hi, a3*inv_hi);
        }
    }
}

// ---------------------------------------------------------------------------
extern "C" void kernel_launch(void* const* d_in, const int* in_sizes, int n_in,
                              void* d_out, int out_size)
{
    const float* X  = (const float*)d_in[0];
    const float* Wq = (const float*)d_in[1];
    const float* bq = (const float*)d_in[2];
    const float* Wk = (const float*)d_in[3];
    const float* bk = (const float*)d_in[4];
    const float* Wv = (const float*)d_in[5];
    const float* bv = (const float*)d_in[6];
    const float* Wo = (const float*)d_in[7];
    const float* bo = (const float*)d_in[8];
    const float* Pk = (const float*)d_in[9];
    const float* Pv = (const float*)d_in[10];
    float* out = (float*)d_out;

    cudaFuncSetAttribute(attn_kernel,
                         cudaFuncAttributeMaxDynamicSharedMemorySize,
                         ATTN_SMEM_BYTES);

    qkv_gemm_kernel<<<dim3(8, 32, 3), 256>>>(X, Wq, bq, Wk, bk, Wv, bv);
    attn_kernel<<<dim3(16, NHEAD, BATCH), 256, ATTN_SMEM_BYTES>>>(Pk, Pv);
    out_gemm_kernel<<<dim3(8, 32), 256>>>(Wo, bo, out);
}

// round 13
// speedup vs baseline: 1.1216x; 1.1216x over previous
#include <cuda_runtime.h>

#define BATCH  8
#define SEQ    512
#define NHEAD  8
#define HDIM   64
#define DMODEL 512
#define NREL   1023
#define ZOFF   511

typedef unsigned long long ull;

// Scratch (allocation-free rule: __device__ globals)
__device__ float g_Q[BATCH*NHEAD*SEQ*HDIM];
__device__ float g_K[BATCH*NHEAD*SEQ*HDIM];
__device__ float g_V[BATCH*NHEAD*SEQ*HDIM];
__device__ float g_ctx[BATCH*SEQ*DMODEL];

// ---- tf32 helpers -----------------------------------------------------------
__device__ __forceinline__ float f2tf(float f) {
    unsigned u;
    asm("cvt.rna.tf32.f32 %0, %1;" : "=r"(u) : "f"(f));
    return __uint_as_float(u);
}

__device__ __forceinline__ void mma_tf32(float* c, const unsigned* a, const unsigned* b) {
    asm("mma.sync.aligned.m16n8k8.row.col.f32.tf32.tf32.f32 "
        "{%0,%1,%2,%3}, {%4,%5,%6,%7}, {%8,%9}, {%0,%1,%2,%3};"
        : "+f"(c[0]), "+f"(c[1]), "+f"(c[2]), "+f"(c[3])
        : "r"(a[0]), "r"(a[1]), "r"(a[2]), "r"(a[3]), "r"(b[0]), "r"(b[1]));
}

// ---------------------------------------------------------------------------
// 128x64x(BK=16) tf32 tensor-core GEMM (round-8 version, validated 85.8us).
// ---------------------------------------------------------------------------
__global__ void __launch_bounds__(256) qkv_gemm_kernel(
    const float* __restrict__ X,
    const float* __restrict__ Wq, const float* __restrict__ bq,
    const float* __restrict__ Wk, const float* __restrict__ bk,
    const float* __restrict__ Wv, const float* __restrict__ bv)
{
    const int z = blockIdx.z;
    const float* __restrict__ W    = (z==0) ? Wq : (z==1) ? Wk : Wv;
    const float* __restrict__ bias = (z==0) ? bq : (z==1) ? bk : bv;
    float* out = (z==0) ? g_Q : (z==1) ? g_K : g_V;

    __shared__ float As[2][16][136];
    __shared__ float Bs[2][16][72];

    const int m0 = blockIdx.y * 128;
    const int n0 = blockIdx.x * 64;
    const int tid = threadIdx.x;
    const int wid = tid >> 5;
    const int lane = tid & 31;
    const int g   = lane >> 2;
    const int tig = lane & 3;
    const int wm = (wid >> 1) * 32;
    const int wn = (wid & 1) * 32;

    const int am = tid >> 2;
    const int ak = (tid & 3) * 4;
    const int bkr = tid >> 4;
    const int bn = (tid & 15) * 4;

    float4 xa0, xa1, wb0;
    float acc[2][4][4];
    #pragma unroll
    for (int mt = 0; mt < 2; mt++)
        #pragma unroll
        for (int nt = 0; nt < 4; nt++)
            #pragma unroll
            for (int c = 0; c < 4; c++) acc[mt][nt][c] = 0.f;

    {
        const float* Xp = X + (size_t)m0 * DMODEL;
        xa0 = *(const float4*)&Xp[(size_t)am * DMODEL + ak];
        xa1 = *(const float4*)&Xp[(size_t)(am + 64) * DMODEL + ak];
        wb0 = *(const float4*)&W[(size_t)bkr * DMODEL + n0 + bn];
        As[0][ak+0][am] = f2tf(xa0.x); As[0][ak+1][am] = f2tf(xa0.y);
        As[0][ak+2][am] = f2tf(xa0.z); As[0][ak+3][am] = f2tf(xa0.w);
        As[0][ak+0][am+64] = f2tf(xa1.x); As[0][ak+1][am+64] = f2tf(xa1.y);
        As[0][ak+2][am+64] = f2tf(xa1.z); As[0][ak+3][am+64] = f2tf(xa1.w);
        Bs[0][bkr][bn+0] = f2tf(wb0.x); Bs[0][bkr][bn+1] = f2tf(wb0.y);
        Bs[0][bkr][bn+2] = f2tf(wb0.z); Bs[0][bkr][bn+3] = f2tf(wb0.w);
    }
    __syncthreads();

    int buf = 0;
    for (int kt = 0; kt < 32; kt++) {
        if (kt < 31) {
            const float* Xp = X + (size_t)m0 * DMODEL + (kt+1)*16;
            xa0 = *(const float4*)&Xp[(size_t)am * DMODEL + ak];
            xa1 = *(const float4*)&Xp[(size_t)(am + 64) * DMODEL + ak];
            wb0 = *(const float4*)&W[((size_t)(kt+1)*16 + bkr) * DMODEL + n0 + bn];
        }
        #pragma unroll
        for (int ks = 0; ks < 16; ks += 8) {
            unsigned afr[2][4], bfr[4][2];
            #pragma unroll
            for (int mt = 0; mt < 2; mt++) {
                afr[mt][0] = __float_as_uint(As[buf][ks+tig  ][wm + mt*16 + g]);
                afr[mt][1] = __float_as_uint(As[buf][ks+tig  ][wm + mt*16 + g + 8]);
                afr[mt][2] = __float_as_uint(As[buf][ks+tig+4][wm + mt*16 + g]);
                afr[mt][3] = __float_as_uint(As[buf][ks+tig+4][wm + mt*16 + g + 8]);
            }
            #pragma unroll
            for (int nt = 0; nt < 4; nt++) {
                bfr[nt][0] = __float_as_uint(Bs[buf][ks+tig  ][wn + nt*8 + g]);
                bfr[nt][1] = __float_as_uint(Bs[buf][ks+tig+4][wn + nt*8 + g]);
            }
            #pragma unroll
            for (int mt = 0; mt < 2; mt++)
                #pragma unroll
                for (int nt = 0; nt < 4; nt++)
                    mma_tf32(acc[mt][nt], afr[mt], bfr[nt]);
        }
        if (kt < 31) {
            int nb = buf ^ 1;
            As[nb][ak+0][am] = f2tf(xa0.x); As[nb][ak+1][am] = f2tf(xa0.y);
            As[nb][ak+2][am] = f2tf(xa0.z); As[nb][ak+3][am] = f2tf(xa0.w);
            As[nb][ak+0][am+64] = f2tf(xa1.x); As[nb][ak+1][am+64] = f2tf(xa1.y);
            As[nb][ak+2][am+64] = f2tf(xa1.z); As[nb][ak+3][am+64] = f2tf(xa1.w);
            Bs[nb][bkr][bn+0] = f2tf(wb0.x); Bs[nb][bkr][bn+1] = f2tf(wb0.y);
            Bs[nb][bkr][bn+2] = f2tf(wb0.z); Bs[nb][bkr][bn+3] = f2tf(wb0.w);
        }
        __syncthreads();
        buf ^= 1;
    }

    const int hh = n0 >> 6;
    #pragma unroll
    for (int mt = 0; mt < 2; mt++) {
        int r0 = m0 + wm + mt*16 + g;
        int r1 = r0 + 8;
        int bb0 = r0 >> 9, ii0 = r0 & 511;
        int bb1 = r1 >> 9, ii1 = r1 & 511;
        float* op0 = &out[(((size_t)(bb0*NHEAD + hh)*SEQ) + ii0)*HDIM];
        float* op1 = &out[(((size_t)(bb1*NHEAD + hh)*SEQ) + ii1)*HDIM];
        #pragma unroll
        for (int nt = 0; nt < 4; nt++) {
            int dd = wn + nt*8 + tig*2;
            int n  = n0 + dd;
            float2 o0 = make_float2(acc[mt][nt][0] + bias[n], acc[mt][nt][1] + bias[n+1]);
            float2 o1 = make_float2(acc[mt][nt][2] + bias[n], acc[mt][nt][3] + bias[n+1]);
            *(float2*)&op0[dd] = o0;
            *(float2*)&op1[dd] = o1;
        }
    }
}

// ---------------------------------------------------------------------------
// Output projection (round-8 version).
// ---------------------------------------------------------------------------
__global__ void __launch_bounds__(256) out_gemm_kernel(
    const float* __restrict__ Wo, const float* __restrict__ bo,
    float* __restrict__ out)
{
    __shared__ float As[2][16][136];
    __shared__ float Bs[2][16][72];

    const int m0 = blockIdx.y * 128;
    const int n0 = blockIdx.x * 64;
    const int tid = threadIdx.x;
    const int wid = tid >> 5;
    const int lane = tid & 31;
    const int g   = lane >> 2;
    const int tig = lane & 3;
    const int wm = (wid >> 1) * 32;
    const int wn = (wid & 1) * 32;

    const int am = tid >> 2;
    const int ak = (tid & 3) * 4;
    const int bkr = tid >> 4;
    const int bn = (tid & 15) * 4;

    float4 xa0, xa1, wb0;
    float acc[2][4][4];
    #pragma unroll
    for (int mt = 0; mt < 2; mt++)
        #pragma unroll
        for (int nt = 0; nt < 4; nt++)
            #pragma unroll
            for (int c = 0; c < 4; c++) acc[mt][nt][c] = 0.f;

    {
        const float* Xp = g_ctx + (size_t)m0 * DMODEL;
        xa0 = *(const float4*)&Xp[(size_t)am * DMODEL + ak];
        xa1 = *(const float4*)&Xp[(size_t)(am + 64) * DMODEL + ak];
        wb0 = *(const float4*)&Wo[(size_t)bkr * DMODEL + n0 + bn];
        As[0][ak+0][am] = f2tf(xa0.x); As[0][ak+1][am] = f2tf(xa0.y);
        As[0][ak+2][am] = f2tf(xa0.z); As[0][ak+3][am] = f2tf(xa0.w);
        As[0][ak+0][am+64] = f2tf(xa1.x); As[0][ak+1][am+64] = f2tf(xa1.y);
        As[0][ak+2][am+64] = f2tf(xa1.z); As[0][ak+3][am+64] = f2tf(xa1.w);
        Bs[0][bkr][bn+0] = f2tf(wb0.x); Bs[0][bkr][bn+1] = f2tf(wb0.y);
        Bs[0][bkr][bn+2] = f2tf(wb0.z); Bs[0][bkr][bn+3] = f2tf(wb0.w);
    }
    __syncthreads();

    int buf = 0;
    for (int kt = 0; kt < 32; kt++) {
        if (kt < 31) {
            const float* Xp = g_ctx + (size_t)m0 * DMODEL + (kt+1)*16;
            xa0 = *(const float4*)&Xp[(size_t)am * DMODEL + ak];
            xa1 = *(const float4*)&Xp[(size_t)(am + 64) * DMODEL + ak];
            wb0 = *(const float4*)&Wo[((size_t)(kt+1)*16 + bkr) * DMODEL + n0 + bn];
        }
        #pragma unroll
        for (int ks = 0; ks < 16; ks += 8) {
            unsigned afr[2][4], bfr[4][2];
            #pragma unroll
            for (int mt = 0; mt < 2; mt++) {
                afr[mt][0] = __float_as_uint(As[buf][ks+tig  ][wm + mt*16 + g]);
                afr[mt][1] = __float_as_uint(As[buf][ks+tig  ][wm + mt*16 + g + 8]);
                afr[mt][2] = __float_as_uint(As[buf][ks+tig+4][wm + mt*16 + g]);
                afr[mt][3] = __float_as_uint(As[buf][ks+tig+4][wm + mt*16 + g + 8]);
            }
            #pragma unroll
            for (int nt = 0; nt < 4; nt++) {
                bfr[nt][0] = __float_as_uint(Bs[buf][ks+tig  ][wn + nt*8 + g]);
                bfr[nt][1] = __float_as_uint(Bs[buf][ks+tig+4][wn + nt*8 + g]);
            }
            #pragma unroll
            for (int mt = 0; mt < 2; mt++)
                #pragma unroll
                for (int nt = 0; nt < 4; nt++)
                    mma_tf32(acc[mt][nt], afr[mt], bfr[nt]);
        }
        if (kt < 31) {
            int nb = buf ^ 1;
            As[nb][ak+0][am] = f2tf(xa0.x); As[nb][ak+1][am] = f2tf(xa0.y);
            As[nb][ak+2][am] = f2tf(xa0.z); As[nb][ak+3][am] = f2tf(xa0.w);
            As[nb][ak+0][am+64] = f2tf(xa1.x); As[nb][ak+1][am+64] = f2tf(xa1.y);
            As[nb][ak+2][am+64] = f2tf(xa1.z); As[nb][ak+3][am+64] = f2tf(xa1.w);
            Bs[nb][bkr][bn+0] = f2tf(wb0.x); Bs[nb][bkr][bn+1] = f2tf(wb0.y);
            Bs[nb][bkr][bn+2] = f2tf(wb0.z); Bs[nb][bkr][bn+3] = f2tf(wb0.w);
        }
        __syncthreads();
        buf ^= 1;
    }

    #pragma unroll
    for (int mt = 0; mt < 2; mt++) {
        int r0 = m0 + wm + mt*16 + g;
        int r1 = r0 + 8;
        #pragma unroll
        for (int nt = 0; nt < 4; nt++) {
            int n = n0 + wn + nt*8 + tig*2;
            float2 o0 = make_float2(acc[mt][nt][0] + bo[n], acc[mt][nt][1] + bo[n+1]);
            float2 o1 = make_float2(acc[mt][nt][2] + bo[n], acc[mt][nt][3] + bo[n+1]);
            *(float2*)&out[(size_t)r0*DMODEL + n] = o0;
            *(float2*)&out[(size_t)r1*DMODEL + n] = o1;
        }
    }
}

// ---------------------------------------------------------------------------
// Fused attention = round-10 version + split dependency chains ONLY
// (score accumulators split by k-half; output split into mix/band chains).
// Layouts, staging, and all indexing identical to round 10.
// ---------------------------------------------------------------------------
#define AOFF_QS   0                      // Qs[64][36]   Q^T tf32      2304
#define AOFF_KS   2304                   // Ks[64][68]   K^T tf32      4352
#define AOFF_VS   6656                   // Vs[64][68]   V tf32        4352
#define AOFF_PVS  11008                  // Pvs[96][68]  Pv band tf32  6528
#define AOFF_SC   17536                  // Sc[32][132]  probs cols 32..95; pads zero
#define AOFF_PK   21760                  // Pks[544]
#define AOFF_S    22304                  // srow[32]
#define ASM_TOT   22336
#define ATTN_SMEM_BYTES (ASM_TOT * 4)    // 89344 B -> 2 CTAs/SM

__global__ void __launch_bounds__(256, 2) attn_kernel(
    const float* __restrict__ Pk, const float* __restrict__ Pv)
{
    extern __shared__ float sm[];
    float* Qs  = sm + AOFF_QS;
    float* Ks  = sm + AOFF_KS;
    float* Vs  = sm + AOFF_VS;
    float* Pvs = sm + AOFF_PVS;
    float* Sc  = sm + AOFF_SC;
    float* Pks = sm + AOFF_PK;
    float* srow = sm + AOFF_S;

    const int i0  = blockIdx.x * 32;
    const int h   = blockIdx.y;
    const int b   = blockIdx.z;
    const int tid = threadIdx.x;
    const int w   = tid >> 5;
    const int lane = tid & 31;
    const int g   = lane >> 2;
    const int tig = lane & 3;
    const int wm  = (w & 1) * 16;
    const int wn  = (w >> 1) * 16;

    const float* Qg = g_Q + (size_t)((b*NHEAD + h)*SEQ) * HDIM;
    const float* Kg = g_K + (size_t)((b*NHEAD + h)*SEQ) * HDIM;
    const float* Vg = g_V + (size_t)((b*NHEAD + h)*SEQ) * HDIM;

    float  kp[16];
    float4 vp[4];
    #pragma unroll
    for (int it = 0; it < 16; it++) {
        int idx = tid + 256*it;
        kp[it] = Kg[(idx >> 6)*HDIM + (idx & 63)];
    }
    #pragma unroll
    for (int it = 0; it < 4; it++) {
        int f4 = tid + 256*it;
        vp[it] = *(const float4*)&Vg[(f4 >> 4)*HDIM + (f4 & 15)*4];
    }

    #pragma unroll
    for (int idx = tid; idx < 32*64; idx += 256) {
        int dd = idx & 63, il = idx >> 6;
        Qs[dd*36 + il] = f2tf(Qg[(i0+il)*HDIM + dd]);
    }
    const int rbase_k = ZOFF - i0 - 31;
    for (int r = tid; r < 543; r += 256)
        Pks[r] = Pk[(rbase_k + r)*NHEAD + h];
    for (int idx = tid; idx < 32*132; idx += 256)
        Sc[idx] = 0.f;
    if (tid < 32) srow[tid] = 0.f;

    // split output accumulators: independent mix / band chains
    float accOm[2][4], accOb[2][4];
    #pragma unroll
    for (int nt = 0; nt < 2; nt++)
        #pragma unroll
        for (int c = 0; c < 4; c++) { accOm[nt][c] = 0.f; accOb[nt][c] = 0.f; }

    __syncthreads();

    for (int jc = 0; jc < 8; jc++) {
        const int j0 = jc * 64;

        const int rbase = ZOFF + j0 - i0 - 31;
        float4 pvl[6];
        #pragma unroll
        for (int it = 0; it < 6; it++) {
            int f4 = tid + 256*it;
            int r = f4 >> 4, dq = f4 & 15;
            int rr = rbase + r;
            rr = (rr < 0) ? 0 : (rr > NREL-1) ? NREL-1 : rr;
            pvl[it] = *(const float4*)&Pv[((size_t)rr*NHEAD + h)*HDIM + dq*4];
        }
        #pragma unroll
        for (int it = 0; it < 16; it++) {
            int idx = tid + 256*it;
            Ks[(idx & 63)*68 + (idx >> 6)] = f2tf(kp[it]);
        }
        #pragma unroll
        for (int it = 0; it < 4; it++) {
            int f4 = tid + 256*it;
            float* vd = &Vs[(f4 >> 4)*68 + (f4 & 15)*4];
            vd[0] = f2tf(vp[it].x); vd[1] = f2tf(vp[it].y);
            vd[2] = f2tf(vp[it].z); vd[3] = f2tf(vp[it].w);
        }
        #pragma unroll
        for (int it = 0; it < 6; it++) {
            int f4 = tid + 256*it;
            float* pd = &Pvs[(f4 >> 4)*68 + (f4 & 15)*4];
            pd[0] = f2tf(pvl[it].x); pd[1] = f2tf(pvl[it].y);
            pd[2] = f2tf(pvl[it].z); pd[3] = f2tf(pvl[it].w);
        }
        __syncthreads();

        if (jc < 7) {
            const int jn = j0 + 64;
            #pragma unroll
            for (int it = 0; it < 16; it++) {
                int idx = tid + 256*it;
                kp[it] = Kg[(jn + (idx >> 6))*HDIM + (idx & 63)];
            }
            #pragma unroll
            for (int it = 0; it < 4; it++) {
                int f4 = tid + 256*it;
                vp[it] = *(const float4*)&Vg[(jn + (f4 >> 4))*HDIM + (f4 & 15)*4];
            }
        }

        // ---- SCORE mma, split chains (k8 0..3 -> scA, 4..7 -> scB) ----
        {
            float scA[2][4], scB[2][4];
            #pragma unroll
            for (int nt = 0; nt < 2; nt++)
                #pragma unroll
                for (int c = 0; c < 4; c++) { scA[nt][c] = 0.f; scB[nt][c] = 0.f; }

            #pragma unroll
            for (int k8 = 0; k8 < 8; k8++) {
                unsigned qa[4], kb[2][2];
                qa[0] = __float_as_uint(Qs[(k8*8+tig  )*36 + wm + g]);
                qa[1] = __float_as_uint(Qs[(k8*8+tig  )*36 + wm + g + 8]);
                qa[2] = __float_as_uint(Qs[(k8*8+tig+4)*36 + wm + g]);
                qa[3] = __float_as_uint(Qs[(k8*8+tig+4)*36 + wm + g + 8]);
                #pragma unroll
                for (int nt = 0; nt < 2; nt++) {
                    kb[nt][0] = __float_as_uint(Ks[(k8*8+tig  )*68 + wn + nt*8 + g]);
                    kb[nt][1] = __float_as_uint(Ks[(k8*8+tig+4)*68 + wn + nt*8 + g]);
                }
                if (k8 < 4) { mma_tf32(scA[0], qa, kb[0]); mma_tf32(scA[1], qa, kb[1]); }
                else        { mma_tf32(scB[0], qa, kb[0]); mma_tf32(scB[1], qa, kb[1]); }
            }

            const int il_lo = wm + g;
            const int il_hi = il_lo + 8;
            float rs_lo = 0.f, rs_hi = 0.f;
            #pragma unroll
            for (int nt = 0; nt < 2; nt++) {
                int jj0 = wn + nt*8 + tig*2;
                float s0 = scA[nt][0] + scB[nt][0];
                float s1 = scA[nt][1] + scB[nt][1];
                float s2 = scA[nt][2] + scB[nt][2];
                float s3 = scA[nt][3] + scB[nt][3];
                float p0 = __expf((s0 + Pks[j0 + jj0     + 31 - il_lo]) * 0.125f);
                float p1 = __expf((s1 + Pks[j0 + jj0 + 1 + 31 - il_lo]) * 0.125f);
                float p2 = __expf((s2 + Pks[j0 + jj0     + 31 - il_hi]) * 0.125f);
                float p3 = __expf((s3 + Pks[j0 + jj0 + 1 + 31 - il_hi]) * 0.125f);
                p0 = f2tf(p0); p1 = f2tf(p1); p2 = f2tf(p2); p3 = f2tf(p3);
                Sc[il_lo*132 + 32 + jj0    ] = p0;
                Sc[il_lo*132 + 32 + jj0 + 1] = p1;
                Sc[il_hi*132 + 32 + jj0    ] = p2;
                Sc[il_hi*132 + 32 + jj0 + 1] = p3;
                rs_lo += p0 + p1;
                rs_hi += p2 + p3;
            }
            rs_lo += __shfl_xor_sync(0xffffffffu, rs_lo, 1);
            rs_lo += __shfl_xor_sync(0xffffffffu, rs_lo, 2);
            rs_hi += __shfl_xor_sync(0xffffffffu, rs_hi, 1);
            rs_hi += __shfl_xor_sync(0xffffffffu, rs_hi, 2);
            if (tig == 0) {
                atomicAdd(&srow[il_lo], rs_lo);
                atomicAdd(&srow[il_hi], rs_hi);
            }
        }
        __syncthreads();

        // ---- MIX mma: accOm += P V ----
        #pragma unroll
        for (int k8 = 0; k8 < 8; k8++) {
            unsigned pa[4], vb[2][2];
            pa[0] = __float_as_uint(Sc[(wm+g  )*132 + 32 + k8*8 + tig]);
            pa[1] = __float_as_uint(Sc[(wm+g+8)*132 + 32 + k8*8 + tig]);
            pa[2] = __float_as_uint(Sc[(wm+g  )*132 + 32 + k8*8 + tig + 4]);
            pa[3] = __float_as_uint(Sc[(wm+g+8)*132 + 32 + k8*8 + tig + 4]);
            #pragma unroll
            for (int nt = 0; nt < 2; nt++) {
                vb[nt][0] = __float_as_uint(Vs[(k8*8+tig  )*68 + wn + nt*8 + g]);
                vb[nt][1] = __float_as_uint(Vs[(k8*8+tig+4)*68 + wn + nt*8 + g]);
            }
            mma_tf32(accOm[0], pa, vb[0]);
            mma_tf32(accOm[1], pa, vb[1]);
        }
        // ---- BAND mma: accOb += Pshift Pvs (A[il][r] = Sc[il][il+r+1]) ----
        #pragma unroll
        for (int k12 = 0; k12 < 12; k12++) {
            unsigned pa[4], vb[2][2];
            const int r0 = k12*8 + tig;
            pa[0] = __float_as_uint(Sc[(wm+g  )*132 + (wm+g  ) + r0 + 1]);
            pa[1] = __float_as_uint(Sc[(wm+g+8)*132 + (wm+g+8) + r0 + 1]);
            pa[2] = __float_as_uint(Sc[(wm+g  )*132 + (wm+g  ) + r0 + 5]);
            pa[3] = __float_as_uint(Sc[(wm+g+8)*132 + (wm+g+8) + r0 + 5]);
            #pragma unroll
            for (int nt = 0; nt < 2; nt++) {
                vb[nt][0] = __float_as_uint(Pvs[(k12*8+tig  )*68 + wn + nt*8 + g]);
                vb[nt][1] = __float_as_uint(Pvs[(k12*8+tig+4)*68 + wn + nt*8 + g]);
            }
            mma_tf32(accOb[0], pa, vb[0]);
            mma_tf32(accOb[1], pa, vb[1]);
        }
        __syncthreads();
    }

    // ---- normalize + write context ----
    {
        const int il_lo = wm + g;
        const int il_hi = il_lo + 8;
        float inv_lo = 1.0f / srow[il_lo];
        float inv_hi = 1.0f / srow[il_hi];
        float* o_lo = &g_ctx[((size_t)(b*SEQ + i0 + il_lo))*DMODEL + h*HDIM];
        float* o_hi = &g_ctx[((size_t)(b*SEQ + i0 + il_hi))*DMODEL + h*HDIM];
        #pragma unroll
        for (int nt = 0; nt < 2; nt++) {
            int dd = wn + nt*8 + tig*2;
            float a0 = accOm[nt][0] + accOb[nt][0];
            float a1 = accOm[nt][1] + accOb[nt][1];
            float a2 = accOm[nt][2] + accOb[nt][2];
            float a3 = accOm[nt][3] + accOb[nt][3];
            *(float2*)&o_lo[dd] = make_float2(a0*inv_lo, a1*inv_lo);
            *(float2*)&o_hi[dd] = make_float2(a2*inv_hi, a3*inv_hi);
        }
    }
}

// ---------------------------------------------------------------------------
extern "C" void kernel_launch(void* const* d_in, const int* in_sizes, int n_in,
                              void* d_out, int out_size)
{
    const float* X  = (const float*)d_in[0];
    const float* Wq = (const float*)d_in[1];
    const float* bq = (const float*)d_in[2];
    const float* Wk = (const float*)d_in[3];
    const float* bk = (const float*)d_in[4];
    const float* Wv = (const float*)d_in[5];
    const float* bv = (const float*)d_in[6];
    const float* Wo = (const float*)d_in[7];
    const float* bo = (const float*)d_in[8];
    const float* Pk = (const float*)d_in[9];
    const float* Pv = (const float*)d_in[10];
    float* out = (float*)d_out;

    cudaFuncSetAttribute(attn_kernel,
                         cudaFuncAttributeMaxDynamicSharedMemorySize,
                         ATTN_SMEM_BYTES);

    qkv_gemm_kernel<<<dim3(8, 32, 3), 256>>>(X, Wq, bq, Wk, bk, Wv, bv);
    attn_kernel<<<dim3(16, NHEAD, BATCH), 256, ATTN_SMEM_BYTES>>>(Pk, Pv);
    out_gemm_kernel<<<dim3(8, 32), 256>>>(Wo, bo, out);
}